// round 16
// baseline (speedup 1.0000x reference)
#include <cuda_runtime.h>

#define BB    16
#define NN    512
#define DDIM  16
#define KNN   20
#define CC    30
#define FF    50
#define NCLS  40
#define NT    256      // threads per block (8 warps)
#define WPB   8
#define QPW   2        // queries per warp, as two straight-line bodies (NOT a loop)
#define BPB   32       // grid.x -> 512 blocks total = single wave at 4 blocks/SM
#define STRIDE 20      // floats per tile row: 16 coords + sq at [16] (conflict-free)
#define FULLM 0xFFFFFFFFu

typedef unsigned long long ull;

// Scratch / precomputed tables (device globals — no allocation allowed)
__device__ float g_feat[BB * NN * DDIM];
__device__ float g_pooled[BB * NN];
__device__ ull   g_Aa[KNN * 32];     // dup2(A[k][f]),    f = 0..31
__device__ ull   g_Ab[KNN * 32];     // dup2(A[k][f+32]), 0 beyond FF

extern __shared__ char smem_raw[];

__device__ __forceinline__ unsigned forder(float f) {
    unsigned u = __float_as_uint(f);
    return u ^ (((unsigned)((int)u >> 31)) | 0x80000000u);
}

__device__ __forceinline__ ull dup2(float v) {
    unsigned u = __float_as_uint(v);
    return ((ull)u << 32) | u;
}

// packed fp32x2 fma: acc = xv2*a2 + acc (two independent IEEE fp32 FMAs)
#define FMA2(acc, xv2, a2) \
    asm("fma.rn.f32x2 %0, %1, %2, %3;" : "=l"(acc) : "l"(xv2), "l"(a2), "l"(acc))

__device__ __forceinline__ float lo32(ull v) { return __uint_as_float((unsigned)v); }
__device__ __forceinline__ float hi32(ull v) { return __uint_as_float((unsigned)(v >> 32)); }

// in-register bitonic sort of 16 u64 keys, ascending.
// (Bitonic i^j form is the ONLY network ptxas reliably keeps in registers —
//  Batcher's variable-bound loops demoted keys[] to local memory; see R15.)
__device__ __forceinline__ void sort16(ull* keys) {
    #pragma unroll
    for (int k = 2; k <= 16; k <<= 1) {
        #pragma unroll
        for (int j = k >> 1; j > 0; j >>= 1) {
            #pragma unroll
            for (int i = 0; i < 16; i++) {
                int l = i ^ j;
                if (l > i) {
                    bool up = ((i & k) == 0);
                    ull a = keys[i], b = keys[l];
                    bool sw = up ? (a > b) : (a < b);
                    keys[i] = sw ? b : a;
                    keys[l] = sw ? a : b;
                }
            }
        }
    }
}

// distances (shifted by -sq[n]: same ordering) of this lane's 16 candidates
// j = lane+32i to query n -> packed (dist,idx) keys. Packed f32x2 dot.
__device__ __forceinline__ void dist16(
    const float* __restrict__ tile, int n, int lane, ull* keys)
{
    const ulonglong2* qp = (const ulonglong2*)(tile + n * STRIDE);
    ulonglong2 qa = qp[0], qb = qp[1];
    const ulonglong2* qp2 = (const ulonglong2*)(tile + n * STRIDE + 8);
    ulonglong2 qc = qp2[0], qd = qp2[1];
    #pragma unroll
    for (int i = 0; i < 16; i++) {
        int j = lane + 32 * i;
        const float* rp = tile + j * STRIDE;
        const ulonglong2* rr = (const ulonglong2*)rp;
        ulonglong2 ra = rr[0], rb = rr[1];
        ull acc = 0ull;
        FMA2(acc, qa.x, ra.x); FMA2(acc, qa.y, ra.y);
        FMA2(acc, qb.x, rb.x); FMA2(acc, qb.y, rb.y);
        const ulonglong2* rr2 = (const ulonglong2*)(rp + 8);
        ulonglong2 rc = rr2[0], rd = rr2[1];
        FMA2(acc, qc.x, rc.x); FMA2(acc, qc.y, rc.y);
        FMA2(acc, qd.x, rd.x); FMA2(acc, qd.y, rd.y);
        float dot  = lo32(acc) + hi32(acc);
        float dist = fmaf(-2.f, dot, rp[16]);   // sq[j] - 2*dot  (order-equivalent)
        keys[i] = ((ull)forder(dist) << 32) | (unsigned)j;
    }
}

// One double-pop tournament round (exact, unique keys; ties -> lowest index ==
// stable jax top_k). Emits winner indices J1, J2 (valid in ALL lanes).
#define TQ_ROUND(keys, J1, J2)                                                  \
    {                                                                           \
        unsigned hi0 = (unsigned)((keys)[0] >> 32), lo0 = (unsigned)(keys)[0];  \
        unsigned hi1 = (unsigned)((keys)[1] >> 32), lo1 = (unsigned)(keys)[1];  \
        unsigned mhi1 = __reduce_min_sync(FULLM, hi0);                          \
        unsigned c1   = (hi0 == mhi1) ? lo0 : FULLM;                            \
        unsigned mlo1 = __reduce_min_sync(FULLM, c1);                           \
        bool win1 = (hi0 == mhi1) && (lo0 == mlo1);                             \
        unsigned chi = win1 ? hi1 : hi0, clo = win1 ? lo1 : lo0;                \
        unsigned mhi2 = __reduce_min_sync(FULLM, chi);                          \
        unsigned c2   = (chi == mhi2) ? clo : FULLM;                            \
        unsigned mlo2 = __reduce_min_sync(FULLM, c2);                           \
        bool win2 = (chi == mhi2) && (clo == mlo2);                             \
        (J1) = mlo1; (J2) = mlo2;                                               \
        int adv = (int)win1 + (int)win2;                                        \
        if (adv) {                                                              \
            _Pragma("unroll")                                                   \
            for (int _i = 0; _i < 15; _i++) (keys)[_i] = (keys)[_i + 1];        \
            (keys)[15] = ~0ull;                                                 \
            if (adv == 2) {                                                     \
                _Pragma("unroll")                                               \
                for (int _i = 0; _i < 15; _i++) (keys)[_i] = (keys)[_i + 1];    \
                (keys)[15] = ~0ull;                                             \
            }                                                                   \
        }                                                                       \
    }

// Exact ranked top-20 (unfused): lane r (r<20) ends holding the index of the
// r-th nearest neighbor.
__device__ __forceinline__ unsigned topk20(ull* keys, int lane)
{
    unsigned sel = 0;
    #pragma unroll
    for (int r = 0; r < KNN / 2; r++) {
        unsigned j1, j2;
        TQ_ROUND(keys, j1, j2);
        if (lane == 2 * r)     sel = j1;
        if (lane == 2 * r + 1) sel = j2;
    }
    return sel;
}

// shared tile setup: load x[b] transposed into [512][20] with sq in column 16.
// sq uses the SAME f32x2 even/odd tree as dist16 -> self-dist = -sq exactly.
__device__ __forceinline__ void load_tile(float* tile, const float4* x4, int tid)
{
    #pragma unroll
    for (int i = tid; i < NN * DDIM / 4; i += NT) {
        int row = i >> 2, part = i & 3;
        *(float4*)(tile + row * STRIDE + part * 4) = x4[i];
    }
    __syncthreads();
    #pragma unroll
    for (int r = tid; r < NN; r += NT) {
        const ulonglong2* rp = (const ulonglong2*)(tile + r * STRIDE);
        ulonglong2 a = rp[0], b = rp[1], c = rp[2], d = rp[3];
        ull acc = 0ull;
        FMA2(acc, a.x, a.x); FMA2(acc, a.y, a.y);
        FMA2(acc, b.x, b.x); FMA2(acc, b.y, b.y);
        FMA2(acc, c.x, c.x); FMA2(acc, c.y, c.y);
        FMA2(acc, d.x, d.x); FMA2(acc, d.y, d.y);
        tile[r * STRIDE + 16] = lo32(acc) + hi32(acc);
    }
}

// one stage-1 query: keys live entirely inside this body (register reuse
// across the two sequential calls — no loop, no interleave; see R14/R5).
__device__ __forceinline__ void s1_query(
    const float* __restrict__ tile, const float* __restrict__ wc,
    int b, int n, int lane)
{
    ull keys[16];
    dist16(tile, n, lane, keys);
    sort16(keys);

    const int d = lane & 15;
    float acc = 0.f;
    #pragma unroll
    for (int r = 0; r < KNN / 2; r++) {
        unsigned j1, j2;
        TQ_ROUND(keys, j1, j2);
        acc = fmaf(wc[2 * r],     tile[j1 * STRIDE + d], acc);
        acc = fmaf(wc[2 * r + 1], tile[j2 * STRIDE + d], acc);
    }
    if (lane < DDIM)
        g_feat[((size_t)b * NN + n) * DDIM + lane] = acc;
}

// ---------------------------------------------------------------------------
// Stage 1: KNN on raw points + weighted Frechet mean fused into the rounds.
// 2 queries per warp as two straight-line bodies; block (0,0) builds tables.
// ---------------------------------------------------------------------------
__global__ void __launch_bounds__(NT, 4) stage1_kernel(
    const float* __restrict__ x, const float* __restrict__ w_fm1,
    const float* __restrict__ w_fm2, const float* __restrict__ w_mix1,
    const float* __restrict__ w_mix2)
{
    float* tile = (float*)smem_raw;                // [512][20]  40960B
    float* wc   = tile + NN * STRIDE;              // [20]          80B
    float* wc2  = wc + KNN;                        // [30][20]    2400B (block 0,0 only)

    const int tid = threadIdx.x, lane = tid & 31, warp = tid >> 5;
    const int b = blockIdx.y;

    load_tile(tile, (const float4*)(x + (size_t)b * NN * DDIM), tid);
    if (tid == 0) {
        float mx = -1e30f;
        for (int k = 0; k < KNN; k++) mx = fmaxf(mx, w_fm1[k]);
        float e[KNN], s = 0.f;
        for (int k = 0; k < KNN; k++) { e[k] = expf(w_fm1[k] - mx); s += e[k]; }
        float inv = 1.f / s;
        for (int k = 0; k < KNN; k++) wc[k] = e[k] * inv;
    }

    // one block builds the stage-2 tables (uniform branch; block-local syncs ok)
    if (blockIdx.x == 0 && blockIdx.y == 0) {
        if (tid < CC) {
            const float* row = w_fm2 + tid * KNN;
            float mx = -1e30f;
            for (int k = 0; k < KNN; k++) mx = fmaxf(mx, row[k]);
            float e[KNN], s = 0.f;
            for (int k = 0; k < KNN; k++) { e[k] = expf(row[k] - mx); s += e[k]; }
            float inv = 1.f / s;
            for (int k = 0; k < KNN; k++) wc2[tid * KNN + k] = e[k] * inv;
        }
        __syncthreads();
        for (int i = tid; i < KNN * 32; i += NT) {
            int k = i >> 5, f = i & 31;
            float a0 = 0.f;
            #pragma unroll
            for (int c = 0; c < CC; c++)
                a0 = fmaf(wc2[c * KNN + k] * __ldg(w_mix1 + c), __ldg(w_mix2 + c * FF + f), a0);
            g_Aa[i] = dup2(a0);
            float a1 = 0.f;
            if (f + 32 < FF) {
                #pragma unroll
                for (int c = 0; c < CC; c++)
                    a1 = fmaf(wc2[c * KNN + k] * __ldg(w_mix1 + c), __ldg(w_mix2 + c * FF + f + 32), a1);
            }
            g_Ab[i] = dup2(a1);
        }
    }
    __syncthreads();

    const int qbase = blockIdx.x * (WPB * QPW) + warp * QPW;
    s1_query(tile, wc, b, qbase,     lane);
    s1_query(tile, wc, b, qbase + 1, lane);
}

// one stage-2 query (straight-line; keys dead before accumulators go live)
__device__ __forceinline__ void s2_query(
    const float* __restrict__ tile, const ull* __restrict__ Aa,
    const ull* __restrict__ Ab, const float* __restrict__ ms,
    int b, int n, int lane)
{
    ull keys[16];
    dist16(tile, n, lane, keys);
    sort16(keys);
    unsigned sel = topk20(keys, lane);

    ull accA[8], accB[8];
    #pragma unroll
    for (int i = 0; i < 8; i++) { accA[i] = 0ull; accB[i] = 0ull; }
    #pragma unroll
    for (int k = 0; k < KNN; k++) {
        unsigned idx = __shfl_sync(FULLM, sel, k);
        ull a0d = Aa[k * 32 + lane];               // (a0,a0)
        ull a1d = Ab[k * 32 + lane];               // (a1,a1) or (0,0)
        const ulonglong2* row = (const ulonglong2*)(tile + idx * STRIDE);
        ulonglong2 p0 = row[0], p1 = row[1];
        FMA2(accA[0], p0.x, a0d); FMA2(accB[0], p0.x, a1d);
        FMA2(accA[1], p0.y, a0d); FMA2(accB[1], p0.y, a1d);
        FMA2(accA[2], p1.x, a0d); FMA2(accB[2], p1.x, a1d);
        FMA2(accA[3], p1.y, a0d); FMA2(accB[3], p1.y, a1d);
        ulonglong2 p2 = row[2], p3 = row[3];
        FMA2(accA[4], p2.x, a0d); FMA2(accB[4], p2.x, a1d);
        FMA2(accA[5], p2.y, a0d); FMA2(accB[5], p2.y, a1d);
        FMA2(accA[6], p3.x, a0d); FMA2(accB[6], p3.x, a1d);
        FMA2(accA[7], p3.y, a0d); FMA2(accB[7], p3.y, a1d);
    }

    const int f0 = lane, f1 = lane + 32;
    const bool v1 = (f1 < FF);
    float s0 = 0.f, s1 = 0.f;
    #pragma unroll
    for (int i = 0; i < 8; i++) {
        float e0 = lo32(accA[i]) - ms[(2 * i)     * FF + f0];
        float e1 = hi32(accA[i]) - ms[(2 * i + 1) * FF + f0];
        s0 = fmaf(e0, e0, s0); s0 = fmaf(e1, e1, s0);
        float e2 = lo32(accB[i]) - (v1 ? ms[(2 * i)     * FF + f1] : 0.f);
        float e3 = hi32(accB[i]) - (v1 ? ms[(2 * i + 1) * FF + f1] : 0.f);
        s1 = fmaf(e2, e2, s1); s1 = fmaf(e3, e3, s1);
    }
    float per = sqrtf(s0 + 1e-8f) + (v1 ? sqrtf(s1 + 1e-8f) : 0.f);
    #pragma unroll
    for (int off = 16; off; off >>= 1)
        per += __shfl_xor_sync(FULLM, per, off);
    if (lane == 0)
        g_pooled[(size_t)b * NN + n] = per * (1.f / (float)FF);
}

// ---------------------------------------------------------------------------
// Stage 2: KNN on g; unfused topk; packed-f32x2 epilogue; 2 sequential queries.
// ---------------------------------------------------------------------------
__global__ void __launch_bounds__(NT, 4) stage2_kernel(
    const float* __restrict__ m_last)
{
    float* tile = (float*)smem_raw;                        // [512][20] = 40960B
    ull*   Aa   = (ull*)(smem_raw + 40960);                // [20][32] dup(a0)   5120B
    ull*   Ab   = (ull*)(smem_raw + 40960 + 5120);         // [20][32] dup(a1)   5120B
    float* ms   = (float*)(smem_raw + 40960 + 10240);      // [16][50]           3200B

    const int tid = threadIdx.x, lane = tid & 31, warp = tid >> 5;
    const int b = blockIdx.y;

    load_tile(tile, (const float4*)(g_feat + (size_t)b * NN * DDIM), tid);
    #pragma unroll
    for (int i = tid; i < KNN * 32; i += NT) { Aa[i] = g_Aa[i]; Ab[i] = g_Ab[i]; }
    for (int i = tid; i < DDIM * FF; i += NT) ms[i] = m_last[i];
    __syncthreads();

    const int qbase = blockIdx.x * (WPB * QPW) + warp * QPW;
    s2_query(tile, Aa, Ab, ms, b, qbase,     lane);
    s2_query(tile, Aa, Ab, ms, b, qbase + 1, lane);
}

// ---------------------------------------------------------------------------
// Final classifier: out[b][j] = sum_n pooled[b][n]*w_cls[n][j] + b_cls[j].
// One block per (b, j): one product per thread + tree reduce (latency ~1 LDG).
// ---------------------------------------------------------------------------
__global__ void __launch_bounds__(NN) cls_kernel(
    const float* __restrict__ w_cls, const float* __restrict__ b_cls,
    float* __restrict__ out)
{
    __shared__ float ws[16];
    const int tid = threadIdx.x, lane = tid & 31, warp = tid >> 5;
    const int b = blockIdx.x, j = blockIdx.y;

    float v = g_pooled[(size_t)b * NN + tid] * __ldg(w_cls + (size_t)tid * NCLS + j);
    #pragma unroll
    for (int off = 16; off; off >>= 1)
        v += __shfl_xor_sync(FULLM, v, off);
    if (lane == 0) ws[warp] = v;
    __syncthreads();
    if (tid < 16) {
        float s = ws[tid];
        #pragma unroll
        for (int off = 8; off; off >>= 1)
            s += __shfl_xor_sync(0xFFFFu, s, off);
        if (tid == 0) out[b * NCLS + j] = s + __ldg(b_cls + j);
    }
}

extern "C" void kernel_launch(void* const* d_in, const int* in_sizes, int n_in,
                              void* d_out, int out_size)
{
    const float* x      = (const float*)d_in[0];  // [16,512,16,1]
    const float* w_fm1  = (const float*)d_in[1];  // [1,20]
    const float* w_mix1 = (const float*)d_in[2];  // [1,30]
    const float* w_fm2  = (const float*)d_in[3];  // [30,20]
    const float* w_mix2 = (const float*)d_in[4];  // [30,50]
    const float* m_last = (const float*)d_in[5];  // [16,50]
    const float* w_cls  = (const float*)d_in[6];  // [512,40]
    const float* b_cls  = (const float*)d_in[7];  // [40]
    float* out = (float*)d_out;                   // [16,40]

    constexpr size_t S1_SMEM = ((size_t)NN * STRIDE + KNN + CC * KNN) * 4;  // 43440
    constexpr size_t S2_SMEM = 40960 + 10240 + 3200;                        // 54400

    cudaFuncSetAttribute(stage1_kernel, cudaFuncAttributeMaxDynamicSharedMemorySize, (int)S1_SMEM);
    cudaFuncSetAttribute(stage2_kernel, cudaFuncAttributeMaxDynamicSharedMemorySize, (int)S2_SMEM);

    dim3 grid(BPB, BB);   // 32 x 16 = 512 blocks, 2 straight-line queries/warp
    stage1_kernel<<<grid, NT, S1_SMEM>>>(x, w_fm1, w_fm2, w_mix1, w_mix2);
    stage2_kernel<<<grid, NT, S2_SMEM>>>(m_last);
    cls_kernel<<<dim3(BB, NCLS), NN>>>(w_cls, b_cls, out);
}

// round 17
// speedup vs baseline: 2.5531x; 2.5531x over previous
#include <cuda_runtime.h>

#define BB    16
#define NN    512
#define DDIM  16
#define KNN   20
#define CC    30
#define FF    50
#define NCLS  40
#define NT    256      // threads per block (8 warps)
#define WPB   8
#define BPB   64       // blocks per batch (grid.x); 1 query per warp
#define STRIDE 20      // floats per tile row: 16 coords + sq at [16] (conflict-free)
#define FULLM 0xFFFFFFFFu

typedef unsigned long long ull;

// Scratch / precomputed tables (device globals — no allocation allowed)
__device__ float g_feat[BB * NN * DDIM];
__device__ float g_pooled[BB * NN];
__device__ ull   g_Aa[KNN * 32];     // dup2(A[k][f]),    f = 0..31
__device__ ull   g_Ab[KNN * 32];     // dup2(A[k][f+32]), 0 beyond FF

extern __shared__ char smem_raw[];

__device__ __forceinline__ unsigned forder(float f) {
    unsigned u = __float_as_uint(f);
    return u ^ (((unsigned)((int)u >> 31)) | 0x80000000u);
}

__device__ __forceinline__ ull dup2(float v) {
    unsigned u = __float_as_uint(v);
    return ((ull)u << 32) | u;
}

// packed fp32x2 fma: acc = xv2*a2 + acc (two independent IEEE fp32 FMAs)
#define FMA2(acc, xv2, a2) \
    asm("fma.rn.f32x2 %0, %1, %2, %3;" : "=l"(acc) : "l"(xv2), "l"(a2), "l"(acc))

__device__ __forceinline__ float lo32(ull v) { return __uint_as_float((unsigned)v); }
__device__ __forceinline__ float hi32(ull v) { return __uint_as_float((unsigned)(v >> 32)); }

// in-register bitonic sort of 16 u64 keys, ascending.
// (Bitonic i^j form is the only network ptxas reliably keeps in registers;
//  Batcher's variable-bound loops demoted keys[] to local memory — R15.)
__device__ __forceinline__ void sort16(ull* keys) {
    #pragma unroll
    for (int k = 2; k <= 16; k <<= 1) {
        #pragma unroll
        for (int j = k >> 1; j > 0; j >>= 1) {
            #pragma unroll
            for (int i = 0; i < 16; i++) {
                int l = i ^ j;
                if (l > i) {
                    bool up = ((i & k) == 0);
                    ull a = keys[i], b = keys[l];
                    bool sw = up ? (a > b) : (a < b);
                    keys[i] = sw ? b : a;
                    keys[l] = sw ? a : b;
                }
            }
        }
    }
}

// distances (shifted by -sq[n]: same ordering) of this lane's 16 candidates
// j = lane+32i to query n -> packed (dist,idx) keys. Packed f32x2 dot.
__device__ __forceinline__ void dist16(
    const float* __restrict__ tile, int n, int lane, ull* keys)
{
    const ulonglong2* qp = (const ulonglong2*)(tile + n * STRIDE);
    ulonglong2 qa = qp[0], qb = qp[1];
    const ulonglong2* qp2 = (const ulonglong2*)(tile + n * STRIDE + 8);
    ulonglong2 qc = qp2[0], qd = qp2[1];
    #pragma unroll
    for (int i = 0; i < 16; i++) {
        int j = lane + 32 * i;
        const float* rp = tile + j * STRIDE;
        const ulonglong2* rr = (const ulonglong2*)rp;
        ulonglong2 ra = rr[0], rb = rr[1];
        ull acc = 0ull;
        FMA2(acc, qa.x, ra.x); FMA2(acc, qa.y, ra.y);
        FMA2(acc, qb.x, rb.x); FMA2(acc, qb.y, rb.y);
        const ulonglong2* rr2 = (const ulonglong2*)(rp + 8);
        ulonglong2 rc = rr2[0], rd = rr2[1];
        FMA2(acc, qc.x, rc.x); FMA2(acc, qc.y, rc.y);
        FMA2(acc, qd.x, rd.x); FMA2(acc, qd.y, rd.y);
        float dot  = lo32(acc) + hi32(acc);
        float dist = fmaf(-2.f, dot, rp[16]);   // sq[j] - 2*dot  (order-equivalent)
        keys[i] = ((ull)forder(dist) << 32) | (unsigned)j;
    }
}

// One double-pop tournament round (exact, unique keys; ties -> lowest index ==
// stable jax top_k). Emits winner indices J1, J2 (valid in ALL lanes).
#define TQ_ROUND(keys, J1, J2)                                                  \
    {                                                                           \
        unsigned hi0 = (unsigned)((keys)[0] >> 32), lo0 = (unsigned)(keys)[0];  \
        unsigned hi1 = (unsigned)((keys)[1] >> 32), lo1 = (unsigned)(keys)[1];  \
        unsigned mhi1 = __reduce_min_sync(FULLM, hi0);                          \
        unsigned c1   = (hi0 == mhi1) ? lo0 : FULLM;                            \
        unsigned mlo1 = __reduce_min_sync(FULLM, c1);                           \
        bool win1 = (hi0 == mhi1) && (lo0 == mlo1);                             \
        unsigned chi = win1 ? hi1 : hi0, clo = win1 ? lo1 : lo0;                \
        unsigned mhi2 = __reduce_min_sync(FULLM, chi);                          \
        unsigned c2   = (chi == mhi2) ? clo : FULLM;                            \
        unsigned mlo2 = __reduce_min_sync(FULLM, c2);                           \
        bool win2 = (chi == mhi2) && (clo == mlo2);                             \
        (J1) = mlo1; (J2) = mlo2;                                               \
        int adv = (int)win1 + (int)win2;                                        \
        if (adv) {                                                              \
            _Pragma("unroll")                                                   \
            for (int _i = 0; _i < 15; _i++) (keys)[_i] = (keys)[_i + 1];        \
            (keys)[15] = ~0ull;                                                 \
            if (adv == 2) {                                                     \
                _Pragma("unroll")                                               \
                for (int _i = 0; _i < 15; _i++) (keys)[_i] = (keys)[_i + 1];    \
                (keys)[15] = ~0ull;                                             \
            }                                                                   \
        }                                                                       \
    }

// Exact ranked top-20 (unfused): lane r (r<20) ends holding the index of the
// r-th nearest neighbor.
__device__ __forceinline__ unsigned topk20(ull* keys, int lane)
{
    unsigned sel = 0;
    #pragma unroll
    for (int r = 0; r < KNN / 2; r++) {
        unsigned j1, j2;
        TQ_ROUND(keys, j1, j2);
        if (lane == 2 * r)     sel = j1;
        if (lane == 2 * r + 1) sel = j2;
    }
    return sel;
}

// shared tile setup: load x[b] transposed into [512][20] with sq in column 16.
// sq uses the SAME f32x2 even/odd tree as dist16 -> self-dist = -sq exactly.
__device__ __forceinline__ void load_tile(float* tile, const float4* x4, int tid)
{
    #pragma unroll
    for (int i = tid; i < NN * DDIM / 4; i += NT) {
        int row = i >> 2, part = i & 3;
        *(float4*)(tile + row * STRIDE + part * 4) = x4[i];
    }
    __syncthreads();
    #pragma unroll
    for (int r = tid; r < NN; r += NT) {
        const ulonglong2* rp = (const ulonglong2*)(tile + r * STRIDE);
        ulonglong2 a = rp[0], b = rp[1], c = rp[2], d = rp[3];
        ull acc = 0ull;
        FMA2(acc, a.x, a.x); FMA2(acc, a.y, a.y);
        FMA2(acc, b.x, b.x); FMA2(acc, b.y, b.y);
        FMA2(acc, c.x, c.x); FMA2(acc, c.y, c.y);
        FMA2(acc, d.x, d.x); FMA2(acc, d.y, d.y);
        tile[r * STRIDE + 16] = lo32(acc) + hi32(acc);
    }
}

// ---------------------------------------------------------------------------
// Stage 1: KNN on raw points + weighted Frechet mean fused into the rounds.
// EXACTLY one query per warp, straight-line body — at the 64-reg budget only
// one keys[16] lifetime may exist per kernel (R14/R16 spills prove this).
// Block (0,0) builds the stage-2 tables.
// ---------------------------------------------------------------------------
__global__ void __launch_bounds__(NT, 4) stage1_kernel(
    const float* __restrict__ x, const float* __restrict__ w_fm1,
    const float* __restrict__ w_fm2, const float* __restrict__ w_mix1,
    const float* __restrict__ w_mix2)
{
    float* tile = (float*)smem_raw;                // [512][20]  40960B
    float* wc   = tile + NN * STRIDE;              // [20]          80B
    float* wc2  = wc + KNN;                        // [30][20]    2400B (block 0,0 only)

    const int tid = threadIdx.x, lane = tid & 31, warp = tid >> 5;
    const int b = blockIdx.y;

    load_tile(tile, (const float4*)(x + (size_t)b * NN * DDIM), tid);
    if (tid == 0) {
        float mx = -1e30f;
        for (int k = 0; k < KNN; k++) mx = fmaxf(mx, w_fm1[k]);
        float e[KNN], s = 0.f;
        for (int k = 0; k < KNN; k++) { e[k] = expf(w_fm1[k] - mx); s += e[k]; }
        float inv = 1.f / s;
        for (int k = 0; k < KNN; k++) wc[k] = e[k] * inv;
    }

    // one block builds the stage-2 tables (uniform branch; block-local syncs ok)
    if (blockIdx.x == 0 && blockIdx.y == 0) {
        if (tid < CC) {
            const float* row = w_fm2 + tid * KNN;
            float mx = -1e30f;
            for (int k = 0; k < KNN; k++) mx = fmaxf(mx, row[k]);
            float e[KNN], s = 0.f;
            for (int k = 0; k < KNN; k++) { e[k] = expf(row[k] - mx); s += e[k]; }
            float inv = 1.f / s;
            for (int k = 0; k < KNN; k++) wc2[tid * KNN + k] = e[k] * inv;
        }
        __syncthreads();
        for (int i = tid; i < KNN * 32; i += NT) {
            int k = i >> 5, f = i & 31;
            float a0 = 0.f;
            #pragma unroll
            for (int c = 0; c < CC; c++)
                a0 = fmaf(wc2[c * KNN + k] * __ldg(w_mix1 + c), __ldg(w_mix2 + c * FF + f), a0);
            g_Aa[i] = dup2(a0);
            float a1 = 0.f;
            if (f + 32 < FF) {
                #pragma unroll
                for (int c = 0; c < CC; c++)
                    a1 = fmaf(wc2[c * KNN + k] * __ldg(w_mix1 + c), __ldg(w_mix2 + c * FF + f + 32), a1);
            }
            g_Ab[i] = dup2(a1);
        }
    }
    __syncthreads();

    const int n = blockIdx.x * WPB + warp;         // 1 query per warp
    ull keys[16];
    dist16(tile, n, lane, keys);
    sort16(keys);

    const int d = lane & 15;
    float acc = 0.f;
    #pragma unroll
    for (int r = 0; r < KNN / 2; r++) {
        unsigned j1, j2;
        TQ_ROUND(keys, j1, j2);
        acc = fmaf(wc[2 * r],     tile[j1 * STRIDE + d], acc);
        acc = fmaf(wc[2 * r + 1], tile[j2 * STRIDE + d], acc);
    }
    if (lane < DDIM)
        g_feat[((size_t)b * NN + n) * DDIM + lane] = acc;
}

// ---------------------------------------------------------------------------
// Stage 2: KNN on g; unfused topk; packed-f32x2 epilogue. 1 query per warp.
// fm2[d,f] = sum_k g[nn_k,d]*A[k,f]; pooled = mean_f ||fm2[:,f]-m_last[:,f]||.
// ---------------------------------------------------------------------------
__global__ void __launch_bounds__(NT, 4) stage2_kernel(
    const float* __restrict__ m_last)
{
    float* tile = (float*)smem_raw;                        // [512][20] = 40960B
    ull*   Aa   = (ull*)(smem_raw + 40960);                // [20][32] dup(a0)   5120B
    ull*   Ab   = (ull*)(smem_raw + 40960 + 5120);         // [20][32] dup(a1)   5120B
    float* ms   = (float*)(smem_raw + 40960 + 10240);      // [16][50]           3200B

    const int tid = threadIdx.x, lane = tid & 31, warp = tid >> 5;
    const int b = blockIdx.y;

    load_tile(tile, (const float4*)(g_feat + (size_t)b * NN * DDIM), tid);
    #pragma unroll
    for (int i = tid; i < KNN * 32; i += NT) { Aa[i] = g_Aa[i]; Ab[i] = g_Ab[i]; }
    for (int i = tid; i < DDIM * FF; i += NT) ms[i] = m_last[i];
    __syncthreads();

    const int n = blockIdx.x * WPB + warp;
    ull keys[16];
    dist16(tile, n, lane, keys);
    sort16(keys);
    unsigned sel = topk20(keys, lane);             // keys dead after this

    ull accA[8], accB[8];
    #pragma unroll
    for (int i = 0; i < 8; i++) { accA[i] = 0ull; accB[i] = 0ull; }
    #pragma unroll
    for (int k = 0; k < KNN; k++) {
        unsigned idx = __shfl_sync(FULLM, sel, k);
        ull a0d = Aa[k * 32 + lane];               // (a0,a0)
        ull a1d = Ab[k * 32 + lane];               // (a1,a1) or (0,0)
        const ulonglong2* row = (const ulonglong2*)(tile + idx * STRIDE);
        ulonglong2 p0 = row[0], p1 = row[1];
        FMA2(accA[0], p0.x, a0d); FMA2(accB[0], p0.x, a1d);
        FMA2(accA[1], p0.y, a0d); FMA2(accB[1], p0.y, a1d);
        FMA2(accA[2], p1.x, a0d); FMA2(accB[2], p1.x, a1d);
        FMA2(accA[3], p1.y, a0d); FMA2(accB[3], p1.y, a1d);
        ulonglong2 p2 = row[2], p3 = row[3];
        FMA2(accA[4], p2.x, a0d); FMA2(accB[4], p2.x, a1d);
        FMA2(accA[5], p2.y, a0d); FMA2(accB[5], p2.y, a1d);
        FMA2(accA[6], p3.x, a0d); FMA2(accB[6], p3.x, a1d);
        FMA2(accA[7], p3.y, a0d); FMA2(accB[7], p3.y, a1d);
    }

    const int f0 = lane, f1 = lane + 32;
    const bool v1 = (f1 < FF);
    float s0 = 0.f, s1 = 0.f;
    #pragma unroll
    for (int i = 0; i < 8; i++) {
        float e0 = lo32(accA[i]) - ms[(2 * i)     * FF + f0];
        float e1 = hi32(accA[i]) - ms[(2 * i + 1) * FF + f0];
        s0 = fmaf(e0, e0, s0); s0 = fmaf(e1, e1, s0);
        float e2 = lo32(accB[i]) - (v1 ? ms[(2 * i)     * FF + f1] : 0.f);
        float e3 = hi32(accB[i]) - (v1 ? ms[(2 * i + 1) * FF + f1] : 0.f);
        s1 = fmaf(e2, e2, s1); s1 = fmaf(e3, e3, s1);
    }
    float per = sqrtf(s0 + 1e-8f) + (v1 ? sqrtf(s1 + 1e-8f) : 0.f);
    #pragma unroll
    for (int off = 16; off; off >>= 1)
        per += __shfl_xor_sync(FULLM, per, off);
    if (lane == 0)
        g_pooled[(size_t)b * NN + n] = per * (1.f / (float)FF);
}

// ---------------------------------------------------------------------------
// Final classifier: out[b][j] = sum_n pooled[b][n]*w_cls[n][j] + b_cls[j].
// One block per (b, j): one product per thread + tree reduce (latency ~1 LDG).
// ---------------------------------------------------------------------------
__global__ void __launch_bounds__(NN) cls_kernel(
    const float* __restrict__ w_cls, const float* __restrict__ b_cls,
    float* __restrict__ out)
{
    __shared__ float ws[16];
    const int tid = threadIdx.x, lane = tid & 31, warp = tid >> 5;
    const int b = blockIdx.x, j = blockIdx.y;

    float v = g_pooled[(size_t)b * NN + tid] * __ldg(w_cls + (size_t)tid * NCLS + j);
    #pragma unroll
    for (int off = 16; off; off >>= 1)
        v += __shfl_xor_sync(FULLM, v, off);
    if (lane == 0) ws[warp] = v;
    __syncthreads();
    if (tid < 16) {
        float s = ws[tid];
        #pragma unroll
        for (int off = 8; off; off >>= 1)
            s += __shfl_xor_sync(0xFFFFu, s, off);
        if (tid == 0) out[b * NCLS + j] = s + __ldg(b_cls + j);
    }
}

extern "C" void kernel_launch(void* const* d_in, const int* in_sizes, int n_in,
                              void* d_out, int out_size)
{
    const float* x      = (const float*)d_in[0];  // [16,512,16,1]
    const float* w_fm1  = (const float*)d_in[1];  // [1,20]
    const float* w_mix1 = (const float*)d_in[2];  // [1,30]
    const float* w_fm2  = (const float*)d_in[3];  // [30,20]
    const float* w_mix2 = (const float*)d_in[4];  // [30,50]
    const float* m_last = (const float*)d_in[5];  // [16,50]
    const float* w_cls  = (const float*)d_in[6];  // [512,40]
    const float* b_cls  = (const float*)d_in[7];  // [40]
    float* out = (float*)d_out;                   // [16,40]

    constexpr size_t S1_SMEM = ((size_t)NN * STRIDE + KNN + CC * KNN) * 4;  // 43440
    constexpr size_t S2_SMEM = 40960 + 10240 + 3200;                        // 54400

    cudaFuncSetAttribute(stage1_kernel, cudaFuncAttributeMaxDynamicSharedMemorySize, (int)S1_SMEM);
    cudaFuncSetAttribute(stage2_kernel, cudaFuncAttributeMaxDynamicSharedMemorySize, (int)S2_SMEM);

    dim3 grid(BPB, BB);   // 64 x 16 = 1024 blocks, 1 query per warp
    stage1_kernel<<<grid, NT, S1_SMEM>>>(x, w_fm1, w_fm2, w_mix1, w_mix2);
    stage2_kernel<<<grid, NT, S2_SMEM>>>(m_last);
    cls_kernel<<<dim3(BB, NCLS), NN>>>(w_cls, b_cls, out);
}